// round 16
// baseline (speedup 1.0000x reference)
#include <cuda_runtime.h>
#include <cuda_bf16.h>
#include <cuda_fp16.h>
#include <cstdint>

// x (12,64,256,256) f32, w (64,64,3,3) f32, out (12,64,256,256) f32
// channel-shift (roll 32 over T*C=192) -> sign -> 3x3 same-pad conv, weights sign(w)*mean|w|[o]
// Persistent: 148 CTAs x 512 thr, tile M=256 px (8x32), N=64, K=576.
// fp8 e4m3 mma.sync m16n8k32 with f32 accum — EXACT: +-1 exact in e4m3,
// integer partial sums <= 576 exact in f32.

#define NT      3072           // 12 images * 32 h-tiles * 8 w-tiles (tile = 8x32 px)
#define GRIDN   148
#define THREADS 512

__device__ float g_scale[64];
__device__ uint2 g_Bpack[9 * 2 * 8 * 32];   // [tap][kt2][nt8][lane] -> (b0,b1) e4m3 frags, 36864 B

// smem: B 36864 | A0 21760 (170 rows * 128B) | A1 21760 | scale 256 = 80640
#define SM_A0    36864
#define SM_A1    58624
#define SM_SC    80384
#define SMEM_DYN 80640

__device__ __forceinline__ uint32_t sign_e4m3(float x) {    // byte: +1 -> 0x38, -1 -> 0xB8, 0 -> 0
    uint32_t u = __float_as_uint(x);
    return (u & 0x7FFFFFFFu) ? (0x38u | ((u >> 24) & 0x80u)) : 0u;
}

// -------------------- weight prep --------------------

__global__ void prep_scale_kernel(const float* __restrict__ w) {
    int o = blockIdx.x, tid = threadIdx.x;
    float s = 0.f;
    for (int i = tid; i < 576; i += 256) s += fabsf(w[o * 576 + i]);
    #pragma unroll
    for (int off = 16; off; off >>= 1) s += __shfl_down_sync(0xFFFFFFFFu, s, off);
    __shared__ float red[8];
    if ((tid & 31) == 0) red[tid >> 5] = s;
    __syncthreads();
    if (tid < 8) {
        float v = red[tid];
        #pragma unroll
        for (int off = 4; off; off >>= 1) v += __shfl_down_sync(0xFFu, v, off);
        if (tid == 0) g_scale[o] = v * (1.0f / 576.0f);
    }
}

// m16n8k32 B-fragment layout (validated in the s8 kernel):
// lane (tig=lane&3, g=lane>>2), col n = g (o = nt*8+g);
// b0 bytes j=0..3: k = 4*tig+j ; b1 bytes j=0..3: k = 16+4*tig+j ; channel = kt*32 + k
__global__ void prep_B_kernel(const float* __restrict__ w) {
    int tap = blockIdx.x;            // 0..8
    int kt  = blockIdx.y;            // 0..1
    int tid = threadIdx.x;           // 256
    int nt = tid >> 5, lane = tid & 31;
    int tig = lane & 3, g = lane >> 2;
    int o = nt * 8 + g;
    uint32_t b0 = 0, b1 = 0;
    #pragma unroll
    for (int j = 0; j < 4; j++) {
        int c0 = kt * 32 + 4 * tig + j;
        int c1 = c0 + 16;
        b0 |= sign_e4m3(w[(o * 64 + c0) * 9 + tap]) << (8 * j);
        b1 |= sign_e4m3(w[(o * 64 + c1) * 9 + tap]) << (8 * j);
    }
    g_Bpack[((tap * 2 + kt) * 8 + nt) * 32 + lane] = make_uint2(b0, b1);
}

// -------------------- A tile layout (validated in the s8 kernel) --------------------
// 10 rows x 34 cols = 340 halo pixels, 64 e4m3 bytes each; pixel-pair 128B rows:
// byte(p, c) = (p>>1)*128 + (((p&1)*64 + c) with 16B-chunk XOR ((p>>1)&7))

__device__ __forceinline__ void load_tile(const float* __restrict__ x, unsigned char* sA,
                                          int tid, int b, int t, int h0, int w0) {
    #pragma unroll
    for (int rep = 0; rep < 2; rep++) {
        int task = tid + rep * 512;
        if (task >= 680) break;
        int half = task & 1;
        int pix = task >> 1;
        int pr = pix / 34, pc = pix - pr * 34;
        int h = h0 - 1 + pr, ww = w0 - 1 + pc;
        bool valid = ((unsigned)h < 256u) && ((unsigned)ww < 256u);
        int fb = t * 64 + half * 32 - 32; if (fb < 0) fb += 192;
        const float* xb = x + (long)(b * 192 + fb) * 65536 + (h * 256 + ww);
        unsigned char* row = sA + (pix >> 1) * 128;
        uint32_t p7 = (uint32_t)((pix >> 1) & 7);
        uint32_t c0 = (uint32_t)((pix & 1) * 4 + half * 2);
        #pragma unroll
        for (int s = 0; s < 4; s++) {
            uint32_t b0 = 0, b1 = 0;
            if (valid) {
                #pragma unroll
                for (int j = 0; j < 4; j++) {
                    b0 |= sign_e4m3(__ldg(xb + ((long)(s * 8 + j) << 16))) << (8 * j);
                    b1 |= sign_e4m3(__ldg(xb + ((long)(s * 8 + 4 + j) << 16))) << (8 * j);
                }
            }
            *reinterpret_cast<uint2*>(row + (((c0 + (s >> 1)) ^ p7) << 4) + (s & 1) * 8) =
                make_uint2(b0, b1);
        }
    }
}

// -------------------- persistent fused kernel --------------------

__global__ void __launch_bounds__(THREADS, 1)
conv_kernel(const float* __restrict__ x, float* __restrict__ out) {
    extern __shared__ unsigned char smem[];
    uint2* sB = reinterpret_cast<uint2*>(smem);
    float* sScale = reinterpret_cast<float*>(smem + SM_SC);

    const int tid = threadIdx.x;
    const int bid = blockIdx.x;

    // stage B once (2304 uint4) + scales
    {
        const uint4* src = reinterpret_cast<const uint4*>(g_Bpack);
        uint4* dst = reinterpret_cast<uint4*>(smem);
        #pragma unroll
        for (int k = 0; k < 5; k++) {
            int idx = tid + k * 512;
            if (idx < 2304) dst[idx] = src[idx];
        }
    }
    if (tid < 64) sScale[tid] = g_scale[tid];

    const int warp = tid >> 5, lane = tid & 31;
    const int ph  = warp >> 1;               // tile row 0..7
    const int pw0 = (warp & 1) * 16;         // tile col base 0/16
    const int tig = lane & 3, g = lane >> 2;
    const int mrow = lane & 15;
    const int h16  = lane >> 4;

    const int n_my = (NT - 1 - bid) / GRIDN + 1;

    // preload tile 0
    {
        int tl = bid;
        int bt = tl >> 8, rem = tl & 255;
        load_tile(x, smem + SM_A0, tid, bt / 3, bt % 3, (rem >> 3) * 8, (rem & 7) * 32);
    }
    __syncthreads();

    for (int it = 0; it < n_my; it++) {
        const int tl = bid + it * GRIDN;
        const int bt = tl >> 8, rem = tl & 255;
        const int h0 = (rem >> 3) * 8, w0 = (rem & 7) * 32;

        // ---- pipelined loader state for tile it+1 ----
        const bool hasnext = (it + 1 < n_my);
        const float* xbp[2];
        unsigned char* rowp[2];
        uint32_t c0a[2], p7a[2];
        bool act[2], vld[2];
        {
            int tl2 = hasnext ? (bid + (it + 1) * GRIDN) : 0;
            int bt2 = tl2 >> 8, rem2 = tl2 & 255;
            int b2 = bt2 / 3, t2 = bt2 % 3;
            int h0n = (rem2 >> 3) * 8, w0n = (rem2 & 7) * 32;
            unsigned char* nbuf = smem + (((it + 1) & 1) ? SM_A1 : SM_A0);
            #pragma unroll
            for (int r = 0; r < 2; r++) {
                int task = tid + r * 512;
                act[r] = hasnext && (task < 680);
                int half = task & 1, pix = (task >> 1) % 340;
                int pr = pix / 34, pc = pix - pr * 34;
                int h = h0n - 1 + pr, ww = w0n - 1 + pc;
                vld[r] = act[r] && ((unsigned)h < 256u) && ((unsigned)ww < 256u);
                int fb = t2 * 64 + half * 32 - 32; if (fb < 0) fb += 192;
                xbp[r] = x + (long)(b2 * 192 + fb) * 65536 + (h * 256 + ww);
                rowp[r] = nbuf + (pix >> 1) * 128;
                c0a[r] = (uint32_t)((pix & 1) * 4 + half * 2);
                p7a[r] = (uint32_t)((pix >> 1) & 7);
            }
        }
        float fl[8];

        // chunk (R, SUB): 8 channels SUB*8.. -> one 8B store
        #define LD_ISSUE(R, SUB) do {                                              \
            if (vld[R]) {                                                          \
                _Pragma("unroll")                                                  \
                for (int m = 0; m < 8; m++)                                        \
                    fl[m] = __ldg(xbp[R] + ((long)((SUB) * 8 + m) << 16));          \
            } else {                                                               \
                _Pragma("unroll")                                                  \
                for (int m = 0; m < 8; m++) fl[m] = 0.f;                           \
            } } while (0)

        #define LD_FLUSH(R, SUB) do {                                              \
            if (act[R]) {                                                          \
                uint32_t b0_ = sign_e4m3(fl[0]) | (sign_e4m3(fl[1]) << 8)           \
                             | (sign_e4m3(fl[2]) << 16) | (sign_e4m3(fl[3]) << 24); \
                uint32_t b1_ = sign_e4m3(fl[4]) | (sign_e4m3(fl[5]) << 8)           \
                             | (sign_e4m3(fl[6]) << 16) | (sign_e4m3(fl[7]) << 24); \
                *reinterpret_cast<uint2*>(rowp[R]                                   \
                    + (((c0a[R] + ((SUB) >> 1)) ^ p7a[R]) << 4) + ((SUB) & 1) * 8)  \
                    = make_uint2(b0_, b1_);                                         \
            } } while (0)

        // ---- mainloop on current buffer ----
        const unsigned char* sA = smem + ((it & 1) ? SM_A1 : SM_A0);
        const uint32_t sA_base = (uint32_t)__cvta_generic_to_shared(sA);

        float acc[8][4];
        #pragma unroll
        for (int nt = 0; nt < 8; nt++) { acc[nt][0]=acc[nt][1]=acc[nt][2]=acc[nt][3]=0.f; }

        LD_ISSUE(0, 0);

        #pragma unroll
        for (int tap = 0; tap < 9; tap++) {
            const int kh = tap / 3, kw = tap - kh * 3;
            const int p = (ph + kh) * 34 + pw0 + kw + mrow;
            const int row = p >> 1;
            const uint32_t sw = ((uint32_t)row & 7u) << 4;
            const uint32_t offp = (uint32_t)((p & 1) * 64 + h16 * 16);
            #pragma unroll
            for (int kt = 0; kt < 2; kt++) {
                uint32_t a0, a1, a2, a3;
                uint32_t addr = sA_base + (uint32_t)row * 128u
                              + ((offp + (uint32_t)(kt * 32)) ^ sw);
                asm volatile("ldmatrix.sync.aligned.x4.m8n8.shared.b16 {%0,%1,%2,%3}, [%4];"
                             : "=r"(a0), "=r"(a1), "=r"(a2), "=r"(a3) : "r"(addr));
                #pragma unroll
                for (int nt = 0; nt < 8; nt++) {
                    uint2 bb = sB[((tap * 2 + kt) * 8 + nt) * 32 + lane];
                    asm volatile(
                        "mma.sync.aligned.m16n8k32.row.col.f32.e4m3.e4m3.f32 "
                        "{%0,%1,%2,%3}, {%4,%5,%6,%7}, {%8,%9}, {%0,%1,%2,%3};"
                        : "+f"(acc[nt][0]), "+f"(acc[nt][1]), "+f"(acc[nt][2]), "+f"(acc[nt][3])
                        : "r"(a0), "r"(a1), "r"(a2), "r"(a3), "r"(bb.x), "r"(bb.y));
                }
            }
            if (tap < 8) {
                const int rp = tap >> 2, sb = tap & 3;
                if (rp == 0) { LD_FLUSH(0, sb); } else { LD_FLUSH(1, sb); }
                const int tn = tap + 1;
                if (tn < 8) {
                    const int rp2 = tn >> 2, sb2 = tn & 3;
                    if (rp2 == 0) { LD_ISSUE(0, sb2); } else { LD_ISSUE(1, sb2); }
                }
            }
        }

        #undef LD_ISSUE
        #undef LD_FLUSH

        // ---- epilogue: scale, store (same mapping as validated kernels) ----
        {
            const int hh = h0 + ph;
            const int wb = w0 + pw0 + g;
            #pragma unroll
            for (int nt = 0; nt < 8; nt++) {
                int o0 = nt * 8 + 2 * tig;
                float s0 = sScale[o0], s1 = sScale[o0 + 1];
                long base0 = ((long)(bt * 64 + o0) << 16) + (hh << 8) + wb;
                long base1 = base0 + 65536;
                out[base0]     = s0 * acc[nt][0];
                out[base1]     = s1 * acc[nt][1];
                out[base0 + 8] = s0 * acc[nt][2];
                out[base1 + 8] = s1 * acc[nt][3];
            }
        }
        __syncthreads();
    }
}

// -------------------- launch --------------------

extern "C" void kernel_launch(void* const* d_in, const int* in_sizes, int n_in,
                              void* d_out, int out_size) {
    const float* x = (const float*)d_in[0];
    const float* w = (const float*)d_in[1];
    float* out = (float*)d_out;

    cudaFuncSetAttribute(conv_kernel, cudaFuncAttributeMaxDynamicSharedMemorySize, SMEM_DYN);

    prep_scale_kernel<<<64, 256>>>(w);
    prep_B_kernel<<<dim3(9, 2, 1), 256>>>(w);
    conv_kernel<<<GRIDN, THREADS, SMEM_DYN>>>(x, out);
}

// round 17
// speedup vs baseline: 1.0770x; 1.0770x over previous
#include <cuda_runtime.h>
#include <cuda_bf16.h>
#include <cuda_fp16.h>
#include <cstdint>

// x (12,64,256,256) f32, w (64,64,3,3) f32, out (12,64,256,256) f32
// channel-shift (roll 32 over T*C=192) -> sign -> 3x3 same-pad conv, weights sign(w)*mean|w|[o]
// Persistent single kernel: 148 CTAs x 512 thr, tile M=256 px (8x32), N=64, K=576.
// fp16 mma m16n8k16, fp16 accum (exact: integer partial sums <= 576 < 2048).
// Weight prep (scale + B fragments) fused into the kernel prologue (no prep launches).
// Loader for tile it+1 software-pipelined through the 9-tap mainloop of tile it.

#define NT      3072           // 12 images * 32 h-tiles * 8 w-tiles (tile = 8x32 px)
#define GRIDN   148
#define THREADS 512

// smem: B 73728 | A0 43520 (340 px * 128B) | A1 43520 | scale 256 = 161024
#define SM_A0    73728
#define SM_A1    117248
#define SM_SC    160768
#define SMEM_DYN 161024

__device__ __forceinline__ uint32_t sign_f16_bits(float x) {
    uint32_t u = __float_as_uint(x);
    uint32_t mag = u & 0x7FFFFFFFu;
    uint32_t s = (u >> 16) & 0x8000u;
    return mag ? (0x3C00u | s) : 0u;     // +-1.0 fp16, 0 if x==0
}

// -------------------- A tile loader (R11/R14-validated) --------------------
// A tile: 10 rows x 34 cols = 340 halo pixels, [pixel][64ch fp16], 128B rows,
// byte(pix, c) = pix*128 + ((2c) ^ ((pix&7)<<4))

__device__ __forceinline__ void load_tile(const float* __restrict__ x, unsigned char* sA,
                                          int tid, int b, int t, int h0, int w0) {
    #pragma unroll
    for (int rep = 0; rep < 2; rep++) {
        int task = tid + rep * 512;
        if (task >= 680) break;
        int half = task & 1;
        int pix = task >> 1;
        int pr = pix / 34, pc = pix - pr * 34;
        int h = h0 - 1 + pr, ww = w0 - 1 + pc;
        bool valid = ((unsigned)h < 256u) && ((unsigned)ww < 256u);
        int fb = t * 64 + half * 32 - 32; if (fb < 0) fb += 192;
        const float* xb = x + (long)(b * 192 + fb) * 65536 + (h * 256 + ww);
        uint32_t wd[16];
        #pragma unroll
        for (int q = 0; q < 16; q++) {
            uint32_t lo = 0, hi = 0;
            if (valid) {
                lo = sign_f16_bits(__ldg(xb + ((long)(2 * q) << 16)));
                hi = sign_f16_bits(__ldg(xb + ((long)(2 * q + 1) << 16)));
            }
            wd[q] = lo | (hi << 16);
        }
        unsigned char* row = sA + pix * 128;
        uint32_t pw7 = (uint32_t)(pix & 7);
        #pragma unroll
        for (int j = 0; j < 4; j++) {
            uint32_t chunk = ((uint32_t)(half * 4 + j)) ^ pw7;
            *reinterpret_cast<uint4*>(row + (chunk << 4)) =
                make_uint4(wd[4 * j], wd[4 * j + 1], wd[4 * j + 2], wd[4 * j + 3]);
        }
    }
}

// -------------------- persistent fused kernel --------------------

__global__ void __launch_bounds__(THREADS, 1)
conv_kernel(const float* __restrict__ x, const float* __restrict__ w,
            float* __restrict__ out) {
    extern __shared__ unsigned char smem[];
    uint2* sB = reinterpret_cast<uint2*>(smem);
    float* sScale = reinterpret_cast<float*>(smem + SM_SC);

    const int tid = threadIdx.x;
    const int bid = blockIdx.x;

    // ---- fused weight prep: B fragments straight from w into smem ----
    // entry idx = ((tap*4+kt)*8+nt)*32+lane ; 9216 entries, 18 per thread
    #pragma unroll
    for (int e = 0; e < 18; e++) {
        int idx = tid + e * 512;
        int lane_ = idx & 31;
        int rest  = idx >> 5;            // 0..287
        int nt_   = rest & 7;
        int tk    = rest >> 3;           // 0..35 = tap*4+kt
        int kt_   = tk & 3, tap_ = tk >> 2;
        int tig_ = lane_ & 3, g_ = lane_ >> 2;
        int o = nt_ * 8 + g_;
        uint32_t ev[4];
        #pragma unroll
        for (int j = 0; j < 4; j++) {
            int k = (j < 2) ? (2 * tig_ + j) : (2 * tig_ + 8 + (j - 2));
            int c = kt_ * 16 + k;
            ev[j] = sign_f16_bits(__ldg(&w[(o * 64 + c) * 9 + tap_]));
        }
        sB[idx] = make_uint2(ev[0] | (ev[1] << 16), ev[2] | (ev[3] << 16));
    }
    // ---- fused scale: o = tid>>3, 8 lanes per outch, shfl-reduce width 8 ----
    {
        int o = tid >> 3, j = tid & 7;
        float s = 0.f;
        #pragma unroll 9
        for (int i = j; i < 576; i += 8) s += fabsf(__ldg(&w[o * 576 + i]));
        s += __shfl_down_sync(0xFFFFFFFFu, s, 4, 8);
        s += __shfl_down_sync(0xFFFFFFFFu, s, 2, 8);
        s += __shfl_down_sync(0xFFFFFFFFu, s, 1, 8);
        if (j == 0) sScale[o] = s * (1.0f / 576.0f);
    }

    const int warp = tid >> 5, lane = tid & 31;
    const int ph  = warp >> 1;               // tile row 0..7
    const int pw0 = (warp & 1) * 16;         // tile col base 0/16
    const int tig = lane & 3, g = lane >> 2;
    const int mrow = lane & 15;
    const int khalf = lane >> 4;

    const int n_my = (NT - 1 - bid) / GRIDN + 1;

    // preload tile 0
    {
        int tl = bid;
        int bt = tl >> 8, rem = tl & 255;
        load_tile(x, smem + SM_A0, tid, bt / 3, bt % 3, (rem >> 3) * 8, (rem & 7) * 32);
    }
    __syncthreads();

    for (int it = 0; it < n_my; it++) {
        const int tl = bid + it * GRIDN;
        const int bt = tl >> 8, rem = tl & 255;
        const int h0 = (rem >> 3) * 8, w0 = (rem & 7) * 32;

        // ---- pipelined loader state for tile it+1 ----
        const bool hasnext = (it + 1 < n_my);
        const float* xbp[2];
        unsigned char* rowp[2];
        uint32_t hb4[2], p7[2];
        bool act[2], vld[2];
        {
            int tl2 = hasnext ? (bid + (it + 1) * GRIDN) : 0;
            int bt2 = tl2 >> 8, rem2 = tl2 & 255;
            int b2 = bt2 / 3, t2 = bt2 % 3;
            int h0n = (rem2 >> 3) * 8, w0n = (rem2 & 7) * 32;
            unsigned char* nbuf = smem + (((it + 1) & 1) ? SM_A1 : SM_A0);
            #pragma unroll
            for (int r = 0; r < 2; r++) {
                int task = tid + r * 512;
                act[r] = hasnext && (task < 680);
                int half = task & 1, pix = (task >> 1) % 340;
                int pr = pix / 34, pc = pix - pr * 34;
                int h = h0n - 1 + pr, ww = w0n - 1 + pc;
                vld[r] = act[r] && ((unsigned)h < 256u) && ((unsigned)ww < 256u);
                int fb = t2 * 64 + half * 32 - 32; if (fb < 0) fb += 192;
                xbp[r] = x + (long)(b2 * 192 + fb) * 65536 + (h * 256 + ww);
                rowp[r] = nbuf + pix * 128;
                hb4[r] = (uint32_t)(half * 4);
                p7[r]  = (uint32_t)(pix & 7);
            }
        }
        float fl[8];

        #define LD_ISSUE(R, SUB) do {                                              \
            if (vld[R]) {                                                          \
                _Pragma("unroll")                                                  \
                for (int m = 0; m < 4; m++) {                                      \
                    int q = (SUB) * 4 + m;                                         \
                    fl[2 * m]     = __ldg(xbp[R] + ((long)(2 * q) << 16));          \
                    fl[2 * m + 1] = __ldg(xbp[R] + ((long)(2 * q + 1) << 16));      \
                }                                                                  \
            } else {                                                               \
                _Pragma("unroll")                                                  \
                for (int m = 0; m < 8; m++) fl[m] = 0.f;                           \
            } } while (0)

        #define LD_FLUSH(R, SUB) do {                                              \
            if (act[R]) {                                                          \
                uint32_t w0_ = sign_f16_bits(fl[0]) | (sign_f16_bits(fl[1]) << 16); \
                uint32_t w1_ = sign_f16_bits(fl[2]) | (sign_f16_bits(fl[3]) << 16); \
                uint32_t w2_ = sign_f16_bits(fl[4]) | (sign_f16_bits(fl[5]) << 16); \
                uint32_t w3_ = sign_f16_bits(fl[6]) | (sign_f16_bits(fl[7]) << 16); \
                uint32_t ch = (hb4[R] + (uint32_t)(SUB)) ^ p7[R];                   \
                *reinterpret_cast<uint4*>(rowp[R] + (ch << 4)) =                    \
                    make_uint4(w0_, w1_, w2_, w3_);                                 \
            } } while (0)

        // ---- mainloop on current buffer, loader chunks interleaved per tap ----
        const unsigned char* sA = smem + ((it & 1) ? SM_A1 : SM_A0);
        const uint32_t sA_base = (uint32_t)__cvta_generic_to_shared(sA);

        uint32_t acc[8][2];
        #pragma unroll
        for (int nt = 0; nt < 8; nt++) { acc[nt][0] = 0u; acc[nt][1] = 0u; }

        LD_ISSUE(0, 0);    // chunk 0 in flight before tap 0

        #pragma unroll
        for (int tap = 0; tap < 9; tap++) {
            const int kh = tap / 3, kw = tap - kh * 3;
            const int pix = (ph + kh) * 34 + pw0 + kw + mrow;
            const uint32_t pix_sw = ((uint32_t)pix & 7u) << 4;
            #pragma unroll
            for (int kt = 0; kt < 4; kt++) {
                uint32_t a0, a1, a2, a3;
                uint32_t addr = sA_base + (uint32_t)pix * 128u
                              + (((uint32_t)(kt * 32 + khalf * 16)) ^ pix_sw);
                asm volatile("ldmatrix.sync.aligned.x4.m8n8.shared.b16 {%0,%1,%2,%3}, [%4];"
                             : "=r"(a0), "=r"(a1), "=r"(a2), "=r"(a3) : "r"(addr));
                #pragma unroll
                for (int nt = 0; nt < 8; nt++) {
                    uint2 bb = sB[((tap * 4 + kt) * 8 + nt) * 32 + lane];
                    asm volatile(
                        "mma.sync.aligned.m16n8k16.row.col.f16.f16.f16.f16 "
                        "{%0,%1}, {%2,%3,%4,%5}, {%6,%7}, {%0,%1};"
                        : "+r"(acc[nt][0]), "+r"(acc[nt][1])
                        : "r"(a0), "r"(a1), "r"(a2), "r"(a3), "r"(bb.x), "r"(bb.y));
                }
            }
            // consume chunk `tap` (loads issued one full tap ago), issue chunk tap+1
            if (tap < 8) {
                const int rp = tap >> 2, sb = tap & 3;
                if (rp == 0) { LD_FLUSH(0, sb); } else { LD_FLUSH(1, sb); }
                const int tn = tap + 1;
                if (tn < 8) {
                    const int rp2 = tn >> 2, sb2 = tn & 3;
                    if (rp2 == 0) { LD_ISSUE(0, sb2); } else { LD_ISSUE(1, sb2); }
                }
            }
        }

        #undef LD_ISSUE
        #undef LD_FLUSH

        // ---- epilogue: unpack half2 (exact integers), scale, store ----
        {
            const int hh = h0 + ph;
            const int wb = w0 + pw0 + g;
            #pragma unroll
            for (int nt = 0; nt < 8; nt++) {
                int o0 = nt * 8 + 2 * tig;
                float s0 = sScale[o0], s1 = sScale[o0 + 1];
                long base0 = ((long)(bt * 64 + o0) << 16) + (hh << 8) + wb;
                long base1 = base0 + 65536;
                float2 f0 = __half22float2(*reinterpret_cast<__half2*>(&acc[nt][0]));
                float2 f1 = __half22float2(*reinterpret_cast<__half2*>(&acc[nt][1]));
                out[base0]     = s0 * f0.x;
                out[base1]     = s1 * f0.y;
                out[base0 + 8] = s0 * f1.x;
                out[base1 + 8] = s1 * f1.y;
            }
        }
        __syncthreads();   // next buffer fully written & visible; current safe to overwrite
    }
}

// -------------------- launch --------------------

extern "C" void kernel_launch(void* const* d_in, const int* in_sizes, int n_in,
                              void* d_out, int out_size) {
    const float* x = (const float*)d_in[0];
    const float* w = (const float*)d_in[1];
    float* out = (float*)d_out;

    cudaFuncSetAttribute(conv_kernel, cudaFuncAttributeMaxDynamicSharedMemorySize, SMEM_DYN);
    conv_kernel<<<GRIDN, THREADS, SMEM_DYN>>>(x, w, out);
}